// round 1
// baseline (speedup 1.0000x reference)
#include <cuda_runtime.h>

// NF4 blockwise quant-dequant (blocksize 512), bit-exact vs the JAX reference.
// One warp handles one 512-element quant block: 32 lanes x 16 elements (4x float4).
// Quantization via a 32-bucket shared LUT: each bucket of width 1/16 over [-1,1]
// contains at most one decision boundary (min midpoint gap 0.0805 > 0.0625), so
// per element: bucket = fma(xn,16,16) -> one LDS.128 -> one exact compare.

__constant__ float c_nf4[16] = {
    -1.0f, -0.6961928009986877f, -0.5250730514526367f, -0.39491748809814453f,
    -0.28444138169288635f, -0.18477343022823334f, -0.09105003625154495f, 0.0f,
    0.07958029955625534f, 0.16093020141124725f, 0.24611230194568634f,
    0.33791524171829224f, 0.4407098591327667f, 0.5626170039176941f,
    0.7229568362236023f, 1.0f};

#define NQB_PER_CTA 8   // 8 warps per CTA, one quant-block each

__device__ __forceinline__ float nf4_one(float xv, float scale, float absmax,
                                         const float4* __restrict__ lut) {
    // IEEE round-to-nearest division: bit-matches the reference's xn = x / scale
    float xn = __fdiv_rn(xv, scale);
    float kf = fmaf(xn, 16.0f, 16.0f);     // bucket in [0, 32]
    int k = (int)kf;                        // trunc; negatives land at 0 after clamp
    k = max(0, min(k, 31));
    float4 e = lut[k];                      // (thr, val_lo, val_hi, -)
    float val = (xn > e.x) ? e.z : e.y;     // exact boundary decision
    return val * absmax;                    // reference multiplies by absmax
}

__global__ __launch_bounds__(256) void nf4_qdq_kernel(
    const float* __restrict__ x, float* __restrict__ out, long long n_qb) {
    __shared__ float4 lut[32];

    // Build the 32-bucket LUT (threads 0..31). Bucket k covers
    // xn in [k/16 - 1, (k+1)/16 - 1); at most one midpoint falls inside.
    if (threadIdx.x < 32) {
        int k = threadIdx.x;
        float lo = (float)k * 0.0625f - 1.0f;
        float hi = lo + 0.0625f;
        int j = 0;
        #pragma unroll
        for (int i = 0; i < 15; i++) {
            float mid = (c_nf4[i] + c_nf4[i + 1]) * 0.5f;  // exact fp32 midpoints
            j += (mid < lo) ? 1 : 0;                        // idx at bucket start
        }
        float thr = __int_as_float(0x7f800000);             // +inf: no boundary
        float vlo = c_nf4[j];
        float vhi = vlo;
        if (j < 15) {
            float mid = (c_nf4[j] + c_nf4[j + 1]) * 0.5f;
            if (mid < hi) { thr = mid; vhi = c_nf4[j + 1]; }
        }
        lut[k] = make_float4(thr, vlo, vhi, 0.0f);
    }
    __syncthreads();

    int warp = threadIdx.x >> 5;
    int lane = threadIdx.x & 31;
    long long qb = (long long)blockIdx.x * NQB_PER_CTA + warp;
    if (qb >= n_qb) return;   // no barriers after this point

    const float4* __restrict__ in4  = (const float4*)(x   + qb * 512);
    float4*       __restrict__ out4 = (float4*)      (out + qb * 512);

    // Load 16 elements per lane (coalesced 128B per instruction)
    float4 v[4];
    #pragma unroll
    for (int i = 0; i < 4; i++) v[i] = in4[i * 32 + lane];

    // Blockwise absmax: register max then warp butterfly (max is order-exact)
    float m = 0.0f;
    #pragma unroll
    for (int i = 0; i < 4; i++) {
        m = fmaxf(m, fabsf(v[i].x));
        m = fmaxf(m, fabsf(v[i].y));
        m = fmaxf(m, fabsf(v[i].z));
        m = fmaxf(m, fabsf(v[i].w));
    }
    #pragma unroll
    for (int s = 16; s; s >>= 1)
        m = fmaxf(m, __shfl_xor_sync(0xffffffffu, m, s));

    float absmax = m;
    float scale  = (absmax == 0.0f) ? 1.0f : absmax;

    #pragma unroll
    for (int i = 0; i < 4; i++) {
        float4 r;
        r.x = nf4_one(v[i].x, scale, absmax, lut);
        r.y = nf4_one(v[i].y, scale, absmax, lut);
        r.z = nf4_one(v[i].z, scale, absmax, lut);
        r.w = nf4_one(v[i].w, scale, absmax, lut);
        out4[i * 32 + lane] = r;
    }
}

extern "C" void kernel_launch(void* const* d_in, const int* in_sizes, int n_in,
                              void* d_out, int out_size) {
    const float* x = (const float*)d_in[0];
    float* out = (float*)d_out;
    long long n = (long long)in_sizes[0];
    long long n_qb = n / 512;                 // n is a multiple of 512 (ref reshapes)
    int grid = (int)((n_qb + NQB_PER_CTA - 1) / NQB_PER_CTA);
    nf4_qdq_kernel<<<grid, 256>>>(x, out, n_qb);
}